// round 16
// baseline (speedup 1.0000x reference)
#include <cuda_runtime.h>
#include <cuda_bf16.h>
#include <cmath>
#include <cstdint>

#define BB 8
#define CC 256
#define HH 80
#define WW 80
#define HW (HH*WW)           // 6400
#define PI_F 3.14159265358979323846f

// conv1x1 GEMM tiling: CTA 128x128x64, warp 64x32, 3-stage, 2 CTAs/SM
#define BM 128
#define BN 128
#define BK 64
#define AST 72               // 64+8 pad
#define BSTR 136             // 128+8 pad
#define ASZ (BM*AST)         // 9216
#define BSZ (BK*BSTR)        // 8704
#define NSTAGE 3
#define GSMEM (NSTAGE*(ASZ+BSZ)*2)   // 107520 bytes -> 2 CTAs/SM

// spectral smem layout (dynamic)
#define SXF  (128*80)
#define SXB  (128*88)
#define STB  (80*88)
#define SPECSMEM (SXF*4 + SXB*2 + STB*2)   // 77568 bytes

// weight segment offsets in bf16 scratch
#define W_PI    0
#define W_F1C   65536        // 512x256 (ffn1 @ fpw)
#define W_COMB  196608       // 256x512 (po @ ffn2)
#define W_POST  327680
#define W_TOTAL 393216

#define NPREP 707            // prep blocks in merged k_pre

// -------------------- scratch (static device globals) --------------------
__device__ __nv_bfloat16  g_h2b[(size_t)BB*CC*HW];
__device__ __nv_bfloat16  g_b1[(size_t)BB*2*CC*HW];
__device__ __nv_bfloat16  g_b2[(size_t)BB*2*CC*HW];
__device__ __nv_bfloat16  g_wbf[W_TOTAL];
__device__ float          g_biasc[CC];
__device__ float          g_biasf1[2*CC];

// fast GELU: tanh form with HW tanh.approx
__device__ __forceinline__ float gelu_fast(float v) {
    const float u = v * fmaf(0.035677408136f, v * v, 0.7978845608028654f);
    float t;
    asm("tanh.approx.f32 %0, %1;" : "=f"(t) : "f"(u));
    return 0.5f * v * (1.0f + t);
}

// -------------------- PTX helpers ----------------------------------------
__device__ __forceinline__ void ldsm4(uint32_t* r, uint32_t addr) {
    asm volatile("ldmatrix.sync.aligned.m8n8.x4.shared.b16 {%0,%1,%2,%3}, [%4];\n"
        : "=r"(r[0]), "=r"(r[1]), "=r"(r[2]), "=r"(r[3]) : "r"(addr));
}
__device__ __forceinline__ void ldsm4t(uint32_t* r, uint32_t addr) {
    asm volatile("ldmatrix.sync.aligned.m8n8.x4.trans.shared.b16 {%0,%1,%2,%3}, [%4];\n"
        : "=r"(r[0]), "=r"(r[1]), "=r"(r[2]), "=r"(r[3]) : "r"(addr));
}
__device__ __forceinline__ void mma16816(float* d, const uint32_t* a, const uint32_t* b) {
    asm volatile(
        "mma.sync.aligned.m16n8k16.row.col.f32.bf16.bf16.f32 "
        "{%0,%1,%2,%3}, {%4,%5,%6,%7}, {%8,%9}, {%0,%1,%2,%3};\n"
        : "+f"(d[0]), "+f"(d[1]), "+f"(d[2]), "+f"(d[3])
        : "r"(a[0]), "r"(a[1]), "r"(a[2]), "r"(a[3]), "r"(b[0]), "r"(b[1]));
}
__device__ __forceinline__ void cpasync16(uint32_t smem, const void* g) {
    asm volatile("cp.async.cg.shared.global [%0], [%1], 16;\n" :: "r"(smem), "l"(g));
}

// ==========================================================================
// k_pre: merged prep + spectral in ONE launch (no cross-block deps).
// ==========================================================================
__global__ __launch_bounds__(256)
void k_pre(const float* __restrict__ pi_w, const float* __restrict__ post_w,
           const float* __restrict__ fpw_w, const float* __restrict__ ffn1_w,
           const float* __restrict__ ffn2_w, const float* __restrict__ po_w,
           const float* __restrict__ ffn1_b, const float* __restrict__ fpw_b,
           const float* __restrict__ po_b, const float* __restrict__ ffn2_b,
           const float* __restrict__ x,
           const float* __restrict__ gamma, const float* __restrict__ beta,
           const float* __restrict__ mean, const float* __restrict__ var,
           const float* __restrict__ ar, const float* __restrict__ ai,
           __nv_bfloat16* __restrict__ wbf,
           float* __restrict__ biasf1, float* __restrict__ biasc,
           __nv_bfloat16* __restrict__ h2b)
{
    __shared__ float arow[4][256];
    __shared__ float tapsS[80];
    extern __shared__ char sm[];

    const int blk = blockIdx.x;
    const int tid = threadIdx.x;

    if (blk < 128) {
        const int r0 = blk * 4;
        for (int i = tid; i < 1024; i += 256)
            arow[i >> 8][i & 255] = ffn1_w[(r0 + (i >> 8)) * 256 + (i & 255)];
        __syncthreads();
        float a0 = 0.f, a1 = 0.f, a2 = 0.f, a3 = 0.f;
        #pragma unroll 8
        for (int k = 0; k < 256; k++) {
            const float bv = fpw_w[(size_t)k * 256 + tid];
            a0 = fmaf(arow[0][k], bv, a0);
            a1 = fmaf(arow[1][k], bv, a1);
            a2 = fmaf(arow[2][k], bv, a2);
            a3 = fmaf(arow[3][k], bv, a3);
        }
        wbf[W_F1C + (size_t)(r0 + 0) * 256 + tid] = __float2bfloat16(a0);
        wbf[W_F1C + (size_t)(r0 + 1) * 256 + tid] = __float2bfloat16(a1);
        wbf[W_F1C + (size_t)(r0 + 2) * 256 + tid] = __float2bfloat16(a2);
        wbf[W_F1C + (size_t)(r0 + 3) * 256 + tid] = __float2bfloat16(a3);
        return;
    } else if (blk < 192) {
        const int r0 = (blk - 128) * 4;
        for (int i = tid; i < 1024; i += 256)
            arow[i >> 8][i & 255] = po_w[(r0 + (i >> 8)) * 256 + (i & 255)];
        __syncthreads();
        float a0 = 0.f, a1 = 0.f, a2 = 0.f, a3 = 0.f;
        float c0 = 0.f, c1 = 0.f, c2 = 0.f, c3 = 0.f;
        #pragma unroll 8
        for (int k = 0; k < 256; k++) {
            const float bv0 = ffn2_w[(size_t)k * 512 + tid];
            const float bv1 = ffn2_w[(size_t)k * 512 + tid + 256];
            a0 = fmaf(arow[0][k], bv0, a0);
            a1 = fmaf(arow[1][k], bv0, a1);
            a2 = fmaf(arow[2][k], bv0, a2);
            a3 = fmaf(arow[3][k], bv0, a3);
            c0 = fmaf(arow[0][k], bv1, c0);
            c1 = fmaf(arow[1][k], bv1, c1);
            c2 = fmaf(arow[2][k], bv1, c2);
            c3 = fmaf(arow[3][k], bv1, c3);
        }
        wbf[W_COMB + (size_t)(r0 + 0) * 512 + tid] = __float2bfloat16(a0);
        wbf[W_COMB + (size_t)(r0 + 1) * 512 + tid] = __float2bfloat16(a1);
        wbf[W_COMB + (size_t)(r0 + 2) * 512 + tid] = __float2bfloat16(a2);
        wbf[W_COMB + (size_t)(r0 + 3) * 512 + tid] = __float2bfloat16(a3);
        wbf[W_COMB + (size_t)(r0 + 0) * 512 + tid + 256] = __float2bfloat16(c0);
        wbf[W_COMB + (size_t)(r0 + 1) * 512 + tid + 256] = __float2bfloat16(c1);
        wbf[W_COMB + (size_t)(r0 + 2) * 512 + tid + 256] = __float2bfloat16(c2);
        wbf[W_COMB + (size_t)(r0 + 3) * 512 + tid + 256] = __float2bfloat16(c3);
        return;
    } else if (blk < 704) {
        const int i = (blk - 192) * 256 + tid;
        if (i < 65536) wbf[W_PI + i] = __float2bfloat16(pi_w[i]);
        else           wbf[W_POST + (i - 65536)] = __float2bfloat16(post_w[i - 65536]);
        return;
    } else if (blk < 706) {
        const int o = (blk - 704) * 256 + tid;
        float s = ffn1_b[o];
        #pragma unroll 4
        for (int m = 0; m < 256; m++)
            s = fmaf(ffn1_w[o * 256 + m], fpw_b[m], s);
        biasf1[o] = s;
        return;
    } else if (blk == 706) {
        const int o = tid;
        float s = po_b[o];
        #pragma unroll 4
        for (int m = 0; m < 256; m++)
            s = fmaf(po_w[o * 256 + m], ffn2_b[m], s);
        biasc[o] = s;
        return;
    }

    // ---------------- spectral branch (self-contained) --------------------
    float* xf = (float*)sm;
    __nv_bfloat16* xb = (__nv_bfloat16*)(sm + SXF * 4);
    __nv_bfloat16* tb = (__nv_bfloat16*)(sm + SXF * 4 + SXB * 2);

    const int rowbase = (blk - NPREP) * 128;
    const float* xg = x + (size_t)rowbase * 80;

    if (tid < 80) {
        float t = 0.0f;
        if (tid & 1) {
            float ang = PI_F * (float)tid / 80.0f;
            t = -(2.0f / 80.0f) * (cosf(ang) / sinf(ang));
        }
        tapsS[tid] = t;
    }

    #pragma unroll
    for (int j = 0; j < 10; j++) {
        const int ci = tid + j * 256;
        const int r = ci / 20, c4 = (ci % 20) * 4;
        const float4 v = *(const float4*)(xg + r * 80 + c4);
        *(float4*)(xf + r * 80 + c4) = v;
        __nv_bfloat162* d = (__nv_bfloat162*)(xb + r * 88 + c4);
        d[0] = __floats2bfloat162_rn(v.x, v.y);
        d[1] = __floats2bfloat162_rn(v.z, v.w);
    }
    __syncthreads();

    #pragma unroll
    for (int j = 0; j < 13; j++) {
        const int ci = tid + j * 256;
        if (ci < 3200) {
            const int r = ci / 40, c2 = (ci % 40) * 2;
            const int d0 = (c2 - r + 80) % 80;
            const int d1 = (c2 + 1 - r + 80) % 80;
            *(__nv_bfloat162*)(tb + r * 88 + c2) =
                __floats2bfloat162_rn(tapsS[d0], tapsS[d1]);
        }
    }
    __syncthreads();

    const int lane = tid & 31, w = tid >> 5;
    const int lr = lane & 15, lc = (lane >> 4) << 3;
    const uint32_t sXb = (uint32_t)__cvta_generic_to_shared(xb);
    const uint32_t sTb = (uint32_t)__cvta_generic_to_shared(tb);

    float acc[10][4];
    #pragma unroll
    for (int j = 0; j < 10; j++)
        #pragma unroll
        for (int k = 0; k < 4; k++) acc[j][k] = 0.0f;

    #pragma unroll
    for (int k = 0; k < 5; k++) {
        uint32_t a[4], b[5][4];
        ldsm4(a, sXb + ((w * 16 + lr) * 88 + k * 16 + lc) * 2);
        #pragma unroll
        for (int nt = 0; nt < 5; nt++)
            ldsm4t(b[nt], sTb + ((k * 16 + lr) * 88 + nt * 16 + lc) * 2);
        #pragma unroll
        for (int n8 = 0; n8 < 10; n8++)
            mma16816(acc[n8], a, &b[n8 >> 1][(n8 & 1) * 2]);
    }

    #pragma unroll
    for (int rg = 0; rg < 2; rg++) {
        const int rl = w * 16 + rg * 8 + (lane >> 2);
        const int grow = rowbase + rl;
        const int ch = (grow / HH) & (CC - 1);
        const float s  = gamma[ch] * rsqrtf(var[ch] + 1e-5f);
        const float tc = beta[ch] - mean[ch] * s;
        const float A  = ar[ch] * s;
        const float Bv = ai[ch] * s;
        const float Cv = ar[ch] * tc;
        __nv_bfloat16* ob = h2b + (size_t)grow * 80;
        #pragma unroll
        for (int n8 = 0; n8 < 10; n8++) {
            const int col = n8 * 8 + (lane & 3) * 2;
            const float u0 = acc[n8][rg * 2 + 0];
            const float u1 = acc[n8][rg * 2 + 1];
            const float x0 = xf[rl * 80 + col];
            const float x1 = xf[rl * 80 + col + 1];
            const float h0 = fmaf(A, x0, fmaf(Bv, u0, Cv));
            const float h1 = fmaf(A, x1, fmaf(Bv, u1, Cv));
            *(__nv_bfloat162*)(ob + col) = __floats2bfloat162_rn(h0, h1);
        }
    }
}

// ==========================================================================
// Kernel 2: tensor-core conv1x1 GEMM.
// CTA 128x128x64, warp tile 64x32, 3-stage cp.async, 2 CTAs/SM,
// single sync per iteration. RES: 0=none, 1=fp32 res, 2=bf16 res.
// ==========================================================================
template<int CIN, int ACT, int RES, int OUTF32>
__global__ __launch_bounds__(256, 2)
void gemm_tc(const __nv_bfloat16* __restrict__ in,
             const __nv_bfloat16* __restrict__ wgt,
             const float* __restrict__ bias,
             const void* __restrict__ res,
             void* __restrict__ outp)
{
    extern __shared__ __nv_bfloat16 smem[];
    __nv_bfloat16* As = smem;
    __nv_bfloat16* Bs = smem + NSTAGE * ASZ;

    const int tid = threadIdx.x;
    const int bn = blockIdx.x * BN;
    const int bm = blockIdx.y * BM;
    const int bz = blockIdx.z;
    const int COUT = gridDim.y << 7;

    const __nv_bfloat16* inb = in + (size_t)bz * CIN * HW;

    const uint32_t sA = (uint32_t)__cvta_generic_to_shared(As);
    const uint32_t sB = (uint32_t)__cvta_generic_to_shared(Bs);

    // A: 128 rows x 64 cols = 1024 chunks, 4/thread
    const int a_r = tid >> 1, a_c = (tid & 1) << 5;   // 0 or 32, quads +q*8
    // B: 64 rows x 128 cols = 1024 chunks, 4/thread
    const int b_k = tid >> 2, b_n = (tid & 3) << 5;   // 0,32,64,96, quads +q*8

    const int lane = tid & 31, wid = tid >> 5;
    const int wm = (wid >> 2) * 64;
    const int wn = (wid & 3) * 32;
    const int lr = lane & 15;
    const int lc = (lane >> 4) << 3;

    float acc[4][4][4];
    #pragma unroll
    for (int i = 0; i < 4; i++)
        #pragma unroll
        for (int j = 0; j < 4; j++)
            #pragma unroll
            for (int k = 0; k < 4; k++) acc[i][j][k] = 0.0f;

    constexpr int NK = CIN / BK;

    auto load_stage = [&](int s, int k0) {
        const uint32_t aOff = sA + s * (ASZ * 2);
        const uint32_t bOff = sB + s * (BSZ * 2);
        #pragma unroll
        for (int q = 0; q < 4; q++)
            cpasync16(aOff + (a_r * AST + a_c + q * 8) * 2,
                      wgt + (size_t)(bm + a_r) * CIN + k0 + a_c + q * 8);
        #pragma unroll
        for (int q = 0; q < 4; q++)
            cpasync16(bOff + (b_k * BSTR + b_n + q * 8) * 2,
                      inb + (size_t)(k0 + b_k) * HW + bn + b_n + q * 8);
        asm volatile("cp.async.commit_group;\n");
    };

    load_stage(0, 0);
    load_stage(1, BK);

    for (int it = 0; it < NK; ++it) {
        asm volatile("cp.async.wait_group 1;\n");
        __syncthreads();

        if (it + 2 < NK) load_stage((it + 2) % NSTAGE, (it + 2) * BK);

        const int s = it % NSTAGE;
        const uint32_t aBase = sA + s * (ASZ * 2);
        const uint32_t bBase = sB + s * (BSZ * 2);

        #pragma unroll
        for (int kk = 0; kk < 4; kk++) {
            uint32_t a[4][4], b[2][4];
            #pragma unroll
            for (int mi = 0; mi < 4; mi++)
                ldsm4(a[mi], aBase + (((wm + mi * 16 + lr) * AST) + kk * 16 + lc) * 2);
            #pragma unroll
            for (int nt = 0; nt < 2; nt++)
                ldsm4t(b[nt], bBase + (((kk * 16 + lr) * BSTR) + wn + nt * 16 + lc) * 2);
            #pragma unroll
            for (int mi = 0; mi < 4; mi++)
                #pragma unroll
                for (int ni = 0; ni < 4; ni++)
                    mma16816(acc[mi][ni], a[mi], &b[ni >> 1][(ni & 1) * 2]);
        }
    }

    #pragma unroll
    for (int mi = 0; mi < 4; mi++) {
        const int m_base = bm + wm + mi * 16 + (lane >> 2);
        #pragma unroll
        for (int rg = 0; rg < 2; rg++) {
            const int mm = m_base + rg * 8;
            const float bv = bias[mm];
            #pragma unroll
            for (int ni = 0; ni < 4; ni++) {
                float v0 = acc[mi][ni][rg * 2 + 0] + bv;
                float v1 = acc[mi][ni][rg * 2 + 1] + bv;
                if (ACT == 1) { v0 = gelu_fast(v0); v1 = gelu_fast(v1); }
                const int n = bn + wn + ni * 8 + (lane & 3) * 2;
                const size_t off = ((size_t)bz * COUT + mm) * HW + n;
                if (RES == 1) {
                    const float2 r = *(const float2*)((const float*)res + off);
                    v0 += r.x; v1 += r.y;
                } else if (RES == 2) {
                    const float2 r = __bfloat1622float2(
                        *(const __nv_bfloat162*)((const __nv_bfloat16*)res + off));
                    v0 += r.x; v1 += r.y;
                }
                if (OUTF32) {
                    float2 o; o.x = v0; o.y = v1;
                    *(float2*)((float*)outp + off) = o;
                } else {
                    __nv_bfloat162 o;
                    o.x = __float2bfloat16(v0); o.y = __float2bfloat16(v1);
                    *(__nv_bfloat162*)((__nv_bfloat16*)outp + off) = o;
                }
            }
        }
    }
}

// ==========================================================================
// Kernel 3: depthwise 3x3 + bias + fast GELU (2 row streams per thread).
// ==========================================================================
__global__ __launch_bounds__(320)
void dwgelu_kernel(const __nv_bfloat16* __restrict__ in,
                   const float* __restrict__ w,
                   const float* __restrict__ b,
                   __nv_bfloat16* __restrict__ out)
{
    __shared__ float pl[82 * 82];
    const int tid = threadIdx.x;
    const int bc = blockIdx.x;
    const int c = bc & (CC - 1);

    if (tid < 82) {
        pl[tid] = 0.0f;
        pl[81 * 82 + tid] = 0.0f;
        pl[tid * 82] = 0.0f;
        pl[tid * 82 + 81] = 0.0f;
    }

    {
        const int w2 = tid % 40;
        const int hl = tid / 40;
        const __nv_bfloat162* src = (const __nv_bfloat162*)(in + (size_t)bc * HW);
        #pragma unroll
        for (int j = 0; j < 10; j++) {
            const int h = hl + 8 * j;
            const float2 f = __bfloat1622float2(src[h * 40 + w2]);
            const int base = (h + 1) * 82 + 2 * w2 + 1;
            pl[base] = f.x;
            pl[base + 1] = f.y;
        }
    }
    __syncthreads();

    const float k0 = w[c*9+0], k1 = w[c*9+1], k2 = w[c*9+2];
    const float k3 = w[c*9+3], k4 = w[c*9+4], k5 = w[c*9+5];
    const float k6 = w[c*9+6], k7 = w[c*9+7], k8 = w[c*9+8];
    const float bv = b[c];

    const int wp = tid % 80;
    const int hq = tid / 80;
    const int hA = hq * 10;
    const int hB = 40 + hq * 10;

    const float* pA = &pl[hA * 82 + wp];
    const float* pB = &pl[hB * 82 + wp];
    float a0 = pA[0],  a1 = pA[1],  a2 = pA[2];
    float b0 = pA[82], b1 = pA[83], b2 = pA[84];
    float d0 = pB[0],  d1 = pB[1],  d2 = pB[2];
    float e0 = pB[82], e1 = pB[83], e2 = pB[84];

    __nv_bfloat16* dstA = out + (size_t)bc * HW + hA * 80 + wp;
    __nv_bfloat16* dstB = out + (size_t)bc * HW + hB * 80 + wp;

    #pragma unroll 5
    for (int j = 0; j < 10; j++) {
        const float* prA = pA + (j + 2) * 82;
        const float* prB = pB + (j + 2) * 82;
        const float cA0 = prA[0], cA1 = prA[1], cA2 = prA[2];
        const float cB0 = prB[0], cB1 = prB[1], cB2 = prB[2];
        float sA = bv, sB = bv;
        sA = fmaf(k0, a0, sA); sA = fmaf(k1, a1, sA); sA = fmaf(k2, a2, sA);
        sB = fmaf(k0, d0, sB); sB = fmaf(k1, d1, sB); sB = fmaf(k2, d2, sB);
        sA = fmaf(k3, b0, sA); sA = fmaf(k4, b1, sA); sA = fmaf(k5, b2, sA);
        sB = fmaf(k3, e0, sB); sB = fmaf(k4, e1, sB); sB = fmaf(k5, e2, sB);
        sA = fmaf(k6, cA0, sA); sA = fmaf(k7, cA1, sA); sA = fmaf(k8, cA2, sA);
        sB = fmaf(k6, cB0, sB); sB = fmaf(k7, cB1, sB); sB = fmaf(k8, cB2, sB);
        dstA[j * 80] = __float2bfloat16(gelu_fast(sA));
        dstB[j * 80] = __float2bfloat16(gelu_fast(sB));
        a0 = b0; a1 = b1; a2 = b2;
        b0 = cA0; b1 = cA1; b2 = cA2;
        d0 = e0; d1 = e1; d2 = e2;
        e0 = cB0; e1 = cB1; e2 = cB2;
    }
}

// ==========================================================================
// launch
// ==========================================================================
extern "C" void kernel_launch(void* const* d_in, const int* in_sizes, int n_in,
                              void* d_out, int out_size)
{
    const float* x        = (const float*)d_in[0];
    const float* bn_gamma = (const float*)d_in[1];
    const float* bn_beta  = (const float*)d_in[2];
    const float* bn_mean  = (const float*)d_in[3];
    const float* bn_var   = (const float*)d_in[4];
    const float* a_real   = (const float*)d_in[5];
    const float* a_imag   = (const float*)d_in[6];
    const float* pi_w     = (const float*)d_in[7];
    const float* pi_b     = (const float*)d_in[8];
    const float* dw_w     = (const float*)d_in[9];
    const float* dw_b     = (const float*)d_in[10];
    const float* fpw_w    = (const float*)d_in[11];
    const float* fpw_b    = (const float*)d_in[12];
    const float* ffn1_w   = (const float*)d_in[13];
    const float* ffn1_b   = (const float*)d_in[14];
    const float* ffn2_w   = (const float*)d_in[15];
    const float* ffn2_b   = (const float*)d_in[16];
    const float* po_w     = (const float*)d_in[17];
    const float* po_b     = (const float*)d_in[18];
    const float* post_w   = (const float*)d_in[19];
    const float* post_b   = (const float*)d_in[20];
    float* out = (float*)d_out;

    float *biasc = nullptr, *biasf1 = nullptr;
    __nv_bfloat16 *h2b = nullptr, *b1 = nullptr, *b2 = nullptr, *wbf = nullptr;
    cudaGetSymbolAddress((void**)&h2b,    g_h2b);
    cudaGetSymbolAddress((void**)&b1,     g_b1);
    cudaGetSymbolAddress((void**)&b2,     g_b2);
    cudaGetSymbolAddress((void**)&wbf,    g_wbf);
    cudaGetSymbolAddress((void**)&biasc,  g_biasc);
    cudaGetSymbolAddress((void**)&biasf1, g_biasf1);

    cudaFuncSetAttribute(gemm_tc<256, 0, 0, 0>, cudaFuncAttributeMaxDynamicSharedMemorySize, GSMEM);
    cudaFuncSetAttribute(gemm_tc<256, 1, 0, 0>, cudaFuncAttributeMaxDynamicSharedMemorySize, GSMEM);
    cudaFuncSetAttribute(gemm_tc<512, 0, 2, 0>, cudaFuncAttributeMaxDynamicSharedMemorySize, GSMEM);
    cudaFuncSetAttribute(gemm_tc<256, 0, 1, 1>, cudaFuncAttributeMaxDynamicSharedMemorySize, GSMEM);
    cudaFuncSetAttribute(k_pre, cudaFuncAttributeMaxDynamicSharedMemorySize, SPECSMEM);

    // 0+1) prep + spectral, single launch
    k_pre<<<NPREP + (BB * CC * HH) / 128, 256, SPECSMEM>>>(
        pi_w, post_w, fpw_w, ffn1_w, ffn2_w, po_w,
        ffn1_b, fpw_b, po_b, ffn2_b,
        x, bn_gamma, bn_beta, bn_mean, bn_var, a_real, a_imag,
        wbf, biasf1, biasc, h2b);

    dim3 g256(HW / BN, CC / BM, BB);        // (50, 2, 8)
    dim3 g512(HW / BN, (2 * CC) / BM, BB);  // (50, 4, 8)

    // 2) proj_in
    gemm_tc<256, 0, 0, 0><<<g256, 256, GSMEM>>>(h2b, wbf + W_PI, pi_b, nullptr, b1);
    // 3) dw3x3 + gelu
    dwgelu_kernel<<<BB * CC, 320>>>(b1, dw_w, dw_b, b2);
    // 4) fused (ffn1 @ fpw): 256 -> 512, gelu
    gemm_tc<256, 1, 0, 0><<<g512, 256, GSMEM>>>(b2, wbf + W_F1C, biasf1, nullptr, b1);
    // 5) combined (po @ ffn2): 512 -> 256, + res2 (h2 bf16)
    gemm_tc<512, 0, 2, 0><<<g256, 256, GSMEM>>>(b1, wbf + W_COMB, biasc, h2b, b2);
    // 6) post conv + outer residual (x fp32), fp32 out
    gemm_tc<256, 0, 1, 1><<<g256, 256, GSMEM>>>(b2, wbf + W_POST, post_b, x, out);
}

// round 17
// speedup vs baseline: 1.1361x; 1.1361x over previous
#include <cuda_runtime.h>
#include <cuda_bf16.h>
#include <cmath>
#include <cstdint>

#define BB 8
#define CC 256
#define HH 80
#define WW 80
#define HW (HH*WW)           // 6400
#define PI_F 3.14159265358979323846f

// conv1x1 GEMM tiling: CTA 128x128x32, warp 64x32, 5-stage, 2 CTAs/SM
#define BM 128
#define BN 128
#define BK 32
#define AST 40
#define BSTR 136
#define ASZ (BM*AST)         // 5120
#define BSZ (BK*BSTR)        // 4352
#define NSTAGE 5
#define GSMEM (NSTAGE*(ASZ+BSZ)*2)   // 94720 bytes -> 2 CTAs/SM

// spectral smem layout (dynamic)
#define SXF  (128*80)
#define SXB  (128*88)
#define STB  (80*88)
#define SPECSMEM (SXF*4 + SXB*2 + STB*2)   // 77568 bytes

// weight segment offsets in bf16 scratch
#define W_PI    0
#define W_F1C   65536        // 512x256 (ffn1 @ fpw)
#define W_COMB  196608       // 256x512 (po @ ffn2)
#define W_POST  327680
#define W_TOTAL 393216

#define NPREP 707            // prep blocks in merged k_pre

// -------------------- scratch (static device globals) --------------------
__device__ __nv_bfloat16  g_h2b[(size_t)BB*CC*HW];
__device__ __nv_bfloat16  g_b1[(size_t)BB*2*CC*HW];
__device__ __nv_bfloat16  g_b2[(size_t)BB*2*CC*HW];
__device__ __nv_bfloat16  g_wbf[W_TOTAL];
__device__ float          g_biasc[CC];
__device__ float          g_biasf1[2*CC];

// fast GELU: tanh form with HW tanh.approx
__device__ __forceinline__ float gelu_fast(float v) {
    const float u = v * fmaf(0.035677408136f, v * v, 0.7978845608028654f);
    float t;
    asm("tanh.approx.f32 %0, %1;" : "=f"(t) : "f"(u));
    return 0.5f * v * (1.0f + t);
}

// -------------------- PTX helpers ----------------------------------------
__device__ __forceinline__ void ldsm4(uint32_t* r, uint32_t addr) {
    asm volatile("ldmatrix.sync.aligned.m8n8.x4.shared.b16 {%0,%1,%2,%3}, [%4];\n"
        : "=r"(r[0]), "=r"(r[1]), "=r"(r[2]), "=r"(r[3]) : "r"(addr));
}
__device__ __forceinline__ void ldsm4t(uint32_t* r, uint32_t addr) {
    asm volatile("ldmatrix.sync.aligned.m8n8.x4.trans.shared.b16 {%0,%1,%2,%3}, [%4];\n"
        : "=r"(r[0]), "=r"(r[1]), "=r"(r[2]), "=r"(r[3]) : "r"(addr));
}
__device__ __forceinline__ void mma16816(float* d, const uint32_t* a, const uint32_t* b) {
    asm volatile(
        "mma.sync.aligned.m16n8k16.row.col.f32.bf16.bf16.f32 "
        "{%0,%1,%2,%3}, {%4,%5,%6,%7}, {%8,%9}, {%0,%1,%2,%3};\n"
        : "+f"(d[0]), "+f"(d[1]), "+f"(d[2]), "+f"(d[3])
        : "r"(a[0]), "r"(a[1]), "r"(a[2]), "r"(a[3]), "r"(b[0]), "r"(b[1]));
}
__device__ __forceinline__ void cpasync16(uint32_t smem, const void* g) {
    asm volatile("cp.async.cg.shared.global [%0], [%1], 16;\n" :: "r"(smem), "l"(g));
}

// ==========================================================================
// k_pre: merged prep + spectral in ONE launch (no cross-block deps).
// ==========================================================================
__global__ __launch_bounds__(256)
void k_pre(const float* __restrict__ pi_w, const float* __restrict__ post_w,
           const float* __restrict__ fpw_w, const float* __restrict__ ffn1_w,
           const float* __restrict__ ffn2_w, const float* __restrict__ po_w,
           const float* __restrict__ ffn1_b, const float* __restrict__ fpw_b,
           const float* __restrict__ po_b, const float* __restrict__ ffn2_b,
           const float* __restrict__ x,
           const float* __restrict__ gamma, const float* __restrict__ beta,
           const float* __restrict__ mean, const float* __restrict__ var,
           const float* __restrict__ ar, const float* __restrict__ ai,
           __nv_bfloat16* __restrict__ wbf,
           float* __restrict__ biasf1, float* __restrict__ biasc,
           __nv_bfloat16* __restrict__ h2b)
{
    __shared__ float arow[4][256];
    __shared__ float tapsS[80];
    extern __shared__ char sm[];

    const int blk = blockIdx.x;
    const int tid = threadIdx.x;

    if (blk < 128) {
        const int r0 = blk * 4;
        for (int i = tid; i < 1024; i += 256)
            arow[i >> 8][i & 255] = ffn1_w[(r0 + (i >> 8)) * 256 + (i & 255)];
        __syncthreads();
        float a0 = 0.f, a1 = 0.f, a2 = 0.f, a3 = 0.f;
        #pragma unroll 8
        for (int k = 0; k < 256; k++) {
            const float bv = fpw_w[(size_t)k * 256 + tid];
            a0 = fmaf(arow[0][k], bv, a0);
            a1 = fmaf(arow[1][k], bv, a1);
            a2 = fmaf(arow[2][k], bv, a2);
            a3 = fmaf(arow[3][k], bv, a3);
        }
        wbf[W_F1C + (size_t)(r0 + 0) * 256 + tid] = __float2bfloat16(a0);
        wbf[W_F1C + (size_t)(r0 + 1) * 256 + tid] = __float2bfloat16(a1);
        wbf[W_F1C + (size_t)(r0 + 2) * 256 + tid] = __float2bfloat16(a2);
        wbf[W_F1C + (size_t)(r0 + 3) * 256 + tid] = __float2bfloat16(a3);
        return;
    } else if (blk < 192) {
        const int r0 = (blk - 128) * 4;
        for (int i = tid; i < 1024; i += 256)
            arow[i >> 8][i & 255] = po_w[(r0 + (i >> 8)) * 256 + (i & 255)];
        __syncthreads();
        float a0 = 0.f, a1 = 0.f, a2 = 0.f, a3 = 0.f;
        float c0 = 0.f, c1 = 0.f, c2 = 0.f, c3 = 0.f;
        #pragma unroll 8
        for (int k = 0; k < 256; k++) {
            const float bv0 = ffn2_w[(size_t)k * 512 + tid];
            const float bv1 = ffn2_w[(size_t)k * 512 + tid + 256];
            a0 = fmaf(arow[0][k], bv0, a0);
            a1 = fmaf(arow[1][k], bv0, a1);
            a2 = fmaf(arow[2][k], bv0, a2);
            a3 = fmaf(arow[3][k], bv0, a3);
            c0 = fmaf(arow[0][k], bv1, c0);
            c1 = fmaf(arow[1][k], bv1, c1);
            c2 = fmaf(arow[2][k], bv1, c2);
            c3 = fmaf(arow[3][k], bv1, c3);
        }
        wbf[W_COMB + (size_t)(r0 + 0) * 512 + tid] = __float2bfloat16(a0);
        wbf[W_COMB + (size_t)(r0 + 1) * 512 + tid] = __float2bfloat16(a1);
        wbf[W_COMB + (size_t)(r0 + 2) * 512 + tid] = __float2bfloat16(a2);
        wbf[W_COMB + (size_t)(r0 + 3) * 512 + tid] = __float2bfloat16(a3);
        wbf[W_COMB + (size_t)(r0 + 0) * 512 + tid + 256] = __float2bfloat16(c0);
        wbf[W_COMB + (size_t)(r0 + 1) * 512 + tid + 256] = __float2bfloat16(c1);
        wbf[W_COMB + (size_t)(r0 + 2) * 512 + tid + 256] = __float2bfloat16(c2);
        wbf[W_COMB + (size_t)(r0 + 3) * 512 + tid + 256] = __float2bfloat16(c3);
        return;
    } else if (blk < 704) {
        const int i = (blk - 192) * 256 + tid;
        if (i < 65536) wbf[W_PI + i] = __float2bfloat16(pi_w[i]);
        else           wbf[W_POST + (i - 65536)] = __float2bfloat16(post_w[i - 65536]);
        return;
    } else if (blk < 706) {
        const int o = (blk - 704) * 256 + tid;
        float s = ffn1_b[o];
        #pragma unroll 4
        for (int m = 0; m < 256; m++)
            s = fmaf(ffn1_w[o * 256 + m], fpw_b[m], s);
        biasf1[o] = s;
        return;
    } else if (blk == 706) {
        const int o = tid;
        float s = po_b[o];
        #pragma unroll 4
        for (int m = 0; m < 256; m++)
            s = fmaf(po_w[o * 256 + m], ffn2_b[m], s);
        biasc[o] = s;
        return;
    }

    // ---------------- spectral branch (self-contained) --------------------
    float* xf = (float*)sm;
    __nv_bfloat16* xb = (__nv_bfloat16*)(sm + SXF * 4);
    __nv_bfloat16* tb = (__nv_bfloat16*)(sm + SXF * 4 + SXB * 2);

    const int rowbase = (blk - NPREP) * 128;
    const float* xg = x + (size_t)rowbase * 80;

    if (tid < 80) {
        float t = 0.0f;
        if (tid & 1) {
            float ang = PI_F * (float)tid / 80.0f;
            t = -(2.0f / 80.0f) * (cosf(ang) / sinf(ang));
        }
        tapsS[tid] = t;
    }

    #pragma unroll
    for (int j = 0; j < 10; j++) {
        const int ci = tid + j * 256;
        const int r = ci / 20, c4 = (ci % 20) * 4;
        const float4 v = *(const float4*)(xg + r * 80 + c4);
        *(float4*)(xf + r * 80 + c4) = v;
        __nv_bfloat162* d = (__nv_bfloat162*)(xb + r * 88 + c4);
        d[0] = __floats2bfloat162_rn(v.x, v.y);
        d[1] = __floats2bfloat162_rn(v.z, v.w);
    }
    __syncthreads();

    #pragma unroll
    for (int j = 0; j < 13; j++) {
        const int ci = tid + j * 256;
        if (ci < 3200) {
            const int r = ci / 40, c2 = (ci % 40) * 2;
            const int d0 = (c2 - r + 80) % 80;
            const int d1 = (c2 + 1 - r + 80) % 80;
            *(__nv_bfloat162*)(tb + r * 88 + c2) =
                __floats2bfloat162_rn(tapsS[d0], tapsS[d1]);
        }
    }
    __syncthreads();

    const int lane = tid & 31, w = tid >> 5;
    const int lr = lane & 15, lc = (lane >> 4) << 3;
    const uint32_t sXb = (uint32_t)__cvta_generic_to_shared(xb);
    const uint32_t sTb = (uint32_t)__cvta_generic_to_shared(tb);

    float acc[10][4];
    #pragma unroll
    for (int j = 0; j < 10; j++)
        #pragma unroll
        for (int k = 0; k < 4; k++) acc[j][k] = 0.0f;

    #pragma unroll
    for (int k = 0; k < 5; k++) {
        uint32_t a[4], b[5][4];
        ldsm4(a, sXb + ((w * 16 + lr) * 88 + k * 16 + lc) * 2);
        #pragma unroll
        for (int nt = 0; nt < 5; nt++)
            ldsm4t(b[nt], sTb + ((k * 16 + lr) * 88 + nt * 16 + lc) * 2);
        #pragma unroll
        for (int n8 = 0; n8 < 10; n8++)
            mma16816(acc[n8], a, &b[n8 >> 1][(n8 & 1) * 2]);
    }

    #pragma unroll
    for (int rg = 0; rg < 2; rg++) {
        const int rl = w * 16 + rg * 8 + (lane >> 2);
        const int grow = rowbase + rl;
        const int ch = (grow / HH) & (CC - 1);
        const float s  = gamma[ch] * rsqrtf(var[ch] + 1e-5f);
        const float tc = beta[ch] - mean[ch] * s;
        const float A  = ar[ch] * s;
        const float Bv = ai[ch] * s;
        const float Cv = ar[ch] * tc;
        __nv_bfloat16* ob = h2b + (size_t)grow * 80;
        #pragma unroll
        for (int n8 = 0; n8 < 10; n8++) {
            const int col = n8 * 8 + (lane & 3) * 2;
            const float u0 = acc[n8][rg * 2 + 0];
            const float u1 = acc[n8][rg * 2 + 1];
            const float x0 = xf[rl * 80 + col];
            const float x1 = xf[rl * 80 + col + 1];
            const float h0 = fmaf(A, x0, fmaf(Bv, u0, Cv));
            const float h1 = fmaf(A, x1, fmaf(Bv, u1, Cv));
            *(__nv_bfloat162*)(ob + col) = __floats2bfloat162_rn(h0, h1);
        }
    }
}

// ==========================================================================
// Kernel 2: tensor-core conv1x1 GEMM.
// CTA 128x128x32 (R14 load mapping), warp tile 64x32, 5-stage cp.async,
// TWO stages computed per wait+sync (halved barrier count), 2 CTAs/SM.
// RES: 0=none, 1=fp32 res, 2=bf16 res.
// ==========================================================================
template<int CIN, int ACT, int RES, int OUTF32>
__global__ __launch_bounds__(256, 2)
void gemm_tc(const __nv_bfloat16* __restrict__ in,
             const __nv_bfloat16* __restrict__ wgt,
             const float* __restrict__ bias,
             const void* __restrict__ res,
             void* __restrict__ outp)
{
    extern __shared__ __nv_bfloat16 smem[];
    __nv_bfloat16* As = smem;
    __nv_bfloat16* Bs = smem + NSTAGE * ASZ;

    const int tid = threadIdx.x;
    const int bn = blockIdx.x * BN;
    const int bm = blockIdx.y * BM;
    const int bz = blockIdx.z;
    const int COUT = gridDim.y << 7;

    const __nv_bfloat16* inb = in + (size_t)bz * CIN * HW;

    const uint32_t sA = (uint32_t)__cvta_generic_to_shared(As);
    const uint32_t sB = (uint32_t)__cvta_generic_to_shared(Bs);

    // R14 proven load mapping: A 128x32 (2 chunks/thr), B 32x128 (2 chunks/thr)
    const int a_r = tid >> 1, a_c = (tid & 1) << 4;
    const int b_k = tid >> 3, b_n = (tid & 7) << 4;

    const int lane = tid & 31, wid = tid >> 5;
    const int wm = (wid >> 2) * 64;
    const int wn = (wid & 3) * 32;
    const int lr = lane & 15;
    const int lc = (lane >> 4) << 3;

    float acc[4][4][4];
    #pragma unroll
    for (int i = 0; i < 4; i++)
        #pragma unroll
        for (int j = 0; j < 4; j++)
            #pragma unroll
            for (int k = 0; k < 4; k++) acc[i][j][k] = 0.0f;

    constexpr int NK = CIN / BK;   // 8 or 16 (even)

    auto load_stage = [&](int s, int k0) {
        const uint32_t aOff = sA + s * (ASZ * 2);
        const uint32_t bOff = sB + s * (BSZ * 2);
        cpasync16(aOff + (a_r * AST + a_c) * 2,
                  wgt + (size_t)(bm + a_r) * CIN + k0 + a_c);
        cpasync16(aOff + (a_r * AST + a_c + 8) * 2,
                  wgt + (size_t)(bm + a_r) * CIN + k0 + a_c + 8);
        cpasync16(bOff + (b_k * BSTR + b_n) * 2,
                  inb + (size_t)(k0 + b_k) * HW + bn + b_n);
        cpasync16(bOff + (b_k * BSTR + b_n + 8) * 2,
                  inb + (size_t)(k0 + b_k) * HW + bn + b_n + 8);
        asm volatile("cp.async.commit_group;\n");
    };

    load_stage(0, 0);
    load_stage(1, BK);
    load_stage(2, 2 * BK);

    #pragma unroll
    for (int it = 0; it < NK; it += 2) {
        // need stages it, it+1 complete. One newer commit (it+2) may be pending
        // except on the last iteration where it+1 is itself the newest.
        if (it + 2 < NK) asm volatile("cp.async.wait_group 1;\n");
        else             asm volatile("cp.async.wait_group 0;\n");
        __syncthreads();

        // prefetch two stages ahead; slots (it+3)%5 == it-2, (it+4)%5 == it-1
        // were fully consumed at iteration it-2 (drained by this sync).
        if (it + 3 < NK) load_stage((it + 3) % NSTAGE, (it + 3) * BK);
        if (it + 4 < NK) load_stage((it + 4) % NSTAGE, (it + 4) * BK);

        #pragma unroll
        for (int half = 0; half < 2; half++) {
            const int s = (it + half) % NSTAGE;
            const uint32_t aBase = sA + s * (ASZ * 2);
            const uint32_t bBase = sB + s * (BSZ * 2);
            #pragma unroll
            for (int kk = 0; kk < 2; kk++) {
                uint32_t a[4][4], b[2][4];
                #pragma unroll
                for (int mi = 0; mi < 4; mi++)
                    ldsm4(a[mi], aBase + (((wm + mi * 16 + lr) * AST) + kk * 16 + lc) * 2);
                #pragma unroll
                for (int nt = 0; nt < 2; nt++)
                    ldsm4t(b[nt], bBase + (((kk * 16 + lr) * BSTR) + wn + nt * 16 + lc) * 2);
                #pragma unroll
                for (int mi = 0; mi < 4; mi++)
                    #pragma unroll
                    for (int ni = 0; ni < 4; ni++)
                        mma16816(acc[mi][ni], a[mi], &b[ni >> 1][(ni & 1) * 2]);
            }
        }
    }

    #pragma unroll
    for (int mi = 0; mi < 4; mi++) {
        const int m_base = bm + wm + mi * 16 + (lane >> 2);
        #pragma unroll
        for (int rg = 0; rg < 2; rg++) {
            const int mm = m_base + rg * 8;
            const float bv = bias[mm];
            #pragma unroll
            for (int ni = 0; ni < 4; ni++) {
                float v0 = acc[mi][ni][rg * 2 + 0] + bv;
                float v1 = acc[mi][ni][rg * 2 + 1] + bv;
                if (ACT == 1) { v0 = gelu_fast(v0); v1 = gelu_fast(v1); }
                const int n = bn + wn + ni * 8 + (lane & 3) * 2;
                const size_t off = ((size_t)bz * COUT + mm) * HW + n;
                if (RES == 1) {
                    const float2 r = *(const float2*)((const float*)res + off);
                    v0 += r.x; v1 += r.y;
                } else if (RES == 2) {
                    const float2 r = __bfloat1622float2(
                        *(const __nv_bfloat162*)((const __nv_bfloat16*)res + off));
                    v0 += r.x; v1 += r.y;
                }
                if (OUTF32) {
                    float2 o; o.x = v0; o.y = v1;
                    *(float2*)((float*)outp + off) = o;
                } else {
                    __nv_bfloat162 o;
                    o.x = __float2bfloat16(v0); o.y = __float2bfloat16(v1);
                    *(__nv_bfloat162*)((__nv_bfloat16*)outp + off) = o;
                }
            }
        }
    }
}

// ==========================================================================
// Kernel 3: depthwise 3x3 + bias + fast GELU (2 row streams per thread).
// ==========================================================================
__global__ __launch_bounds__(320)
void dwgelu_kernel(const __nv_bfloat16* __restrict__ in,
                   const float* __restrict__ w,
                   const float* __restrict__ b,
                   __nv_bfloat16* __restrict__ out)
{
    __shared__ float pl[82 * 82];
    const int tid = threadIdx.x;
    const int bc = blockIdx.x;
    const int c = bc & (CC - 1);

    if (tid < 82) {
        pl[tid] = 0.0f;
        pl[81 * 82 + tid] = 0.0f;
        pl[tid * 82] = 0.0f;
        pl[tid * 82 + 81] = 0.0f;
    }

    {
        const int w2 = tid % 40;
        const int hl = tid / 40;
        const __nv_bfloat162* src = (const __nv_bfloat162*)(in + (size_t)bc * HW);
        #pragma unroll
        for (int j = 0; j < 10; j++) {
            const int h = hl + 8 * j;
            const float2 f = __bfloat1622float2(src[h * 40 + w2]);
            const int base = (h + 1) * 82 + 2 * w2 + 1;
            pl[base] = f.x;
            pl[base + 1] = f.y;
        }
    }
    __syncthreads();

    const float k0 = w[c*9+0], k1 = w[c*9+1], k2 = w[c*9+2];
    const float k3 = w[c*9+3], k4 = w[c*9+4], k5 = w[c*9+5];
    const float k6 = w[c*9+6], k7 = w[c*9+7], k8 = w[c*9+8];
    const float bv = b[c];

    const int wp = tid % 80;
    const int hq = tid / 80;
    const int hA = hq * 10;
    const int hB = 40 + hq * 10;

    const float* pA = &pl[hA * 82 + wp];
    const float* pB = &pl[hB * 82 + wp];
    float a0 = pA[0],  a1 = pA[1],  a2 = pA[2];
    float b0 = pA[82], b1 = pA[83], b2 = pA[84];
    float d0 = pB[0],  d1 = pB[1],  d2 = pB[2];
    float e0 = pB[82], e1 = pB[83], e2 = pB[84];

    __nv_bfloat16* dstA = out + (size_t)bc * HW + hA * 80 + wp;
    __nv_bfloat16* dstB = out + (size_t)bc * HW + hB * 80 + wp;

    #pragma unroll 5
    for (int j = 0; j < 10; j++) {
        const float* prA = pA + (j + 2) * 82;
        const float* prB = pB + (j + 2) * 82;
        const float cA0 = prA[0], cA1 = prA[1], cA2 = prA[2];
        const float cB0 = prB[0], cB1 = prB[1], cB2 = prB[2];
        float sA = bv, sB = bv;
        sA = fmaf(k0, a0, sA); sA = fmaf(k1, a1, sA); sA = fmaf(k2, a2, sA);
        sB = fmaf(k0, d0, sB); sB = fmaf(k1, d1, sB); sB = fmaf(k2, d2, sB);
        sA = fmaf(k3, b0, sA); sA = fmaf(k4, b1, sA); sA = fmaf(k5, b2, sA);
        sB = fmaf(k3, e0, sB); sB = fmaf(k4, e1, sB); sB = fmaf(k5, e2, sB);
        sA = fmaf(k6, cA0, sA); sA = fmaf(k7, cA1, sA); sA = fmaf(k8, cA2, sA);
        sB = fmaf(k6, cB0, sB); sB = fmaf(k7, cB1, sB); sB = fmaf(k8, cB2, sB);
        dstA[j * 80] = __float2bfloat16(gelu_fast(sA));
        dstB[j * 80] = __float2bfloat16(gelu_fast(sB));
        a0 = b0; a1 = b1; a2 = b2;
        b0 = cA0; b1 = cA1; b2 = cA2;
        d0 = e0; d1 = e1; d2 = e2;
        e0 = cB0; e1 = cB1; e2 = cB2;
    }
}

// ==========================================================================
// launch
// ==========================================================================
extern "C" void kernel_launch(void* const* d_in, const int* in_sizes, int n_in,
                              void* d_out, int out_size)
{
    const float* x        = (const float*)d_in[0];
    const float* bn_gamma = (const float*)d_in[1];
    const float* bn_beta  = (const float*)d_in[2];
    const float* bn_mean  = (const float*)d_in[3];
    const float* bn_var   = (const float*)d_in[4];
    const float* a_real   = (const float*)d_in[5];
    const float* a_imag   = (const float*)d_in[6];
    const float* pi_w     = (const float*)d_in[7];
    const float* pi_b     = (const float*)d_in[8];
    const float* dw_w     = (const float*)d_in[9];
    const float* dw_b     = (const float*)d_in[10];
    const float* fpw_w    = (const float*)d_in[11];
    const float* fpw_b    = (const float*)d_in[12];
    const float* ffn1_w   = (const float*)d_in[13];
    const float* ffn1_b   = (const float*)d_in[14];
    const float* ffn2_w   = (const float*)d_in[15];
    const float* ffn2_b   = (const float*)d_in[16];
    const float* po_w     = (const float*)d_in[17];
    const float* po_b     = (const float*)d_in[18];
    const float* post_w   = (const float*)d_in[19];
    const float* post_b   = (const float*)d_in[20];
    float* out = (float*)d_out;

    float *biasc = nullptr, *biasf1 = nullptr;
    __nv_bfloat16 *h2b = nullptr, *b1 = nullptr, *b2 = nullptr, *wbf = nullptr;
    cudaGetSymbolAddress((void**)&h2b,    g_h2b);
    cudaGetSymbolAddress((void**)&b1,     g_b1);
    cudaGetSymbolAddress((void**)&b2,     g_b2);
    cudaGetSymbolAddress((void**)&wbf,    g_wbf);
    cudaGetSymbolAddress((void**)&biasc,  g_biasc);
    cudaGetSymbolAddress((void**)&biasf1, g_biasf1);

    cudaFuncSetAttribute(gemm_tc<256, 0, 0, 0>, cudaFuncAttributeMaxDynamicSharedMemorySize, GSMEM);
    cudaFuncSetAttribute(gemm_tc<256, 1, 0, 0>, cudaFuncAttributeMaxDynamicSharedMemorySize, GSMEM);
    cudaFuncSetAttribute(gemm_tc<512, 0, 2, 0>, cudaFuncAttributeMaxDynamicSharedMemorySize, GSMEM);
    cudaFuncSetAttribute(gemm_tc<256, 0, 1, 1>, cudaFuncAttributeMaxDynamicSharedMemorySize, GSMEM);
    cudaFuncSetAttribute(k_pre, cudaFuncAttributeMaxDynamicSharedMemorySize, SPECSMEM);

    // 0+1) prep + spectral, single launch
    k_pre<<<NPREP + (BB * CC * HH) / 128, 256, SPECSMEM>>>(
        pi_w, post_w, fpw_w, ffn1_w, ffn2_w, po_w,
        ffn1_b, fpw_b, po_b, ffn2_b,
        x, bn_gamma, bn_beta, bn_mean, bn_var, a_real, a_imag,
        wbf, biasf1, biasc, h2b);

    dim3 g256(HW / BN, CC / BM, BB);        // (50, 2, 8)
    dim3 g512(HW / BN, (2 * CC) / BM, BB);  // (50, 4, 8)

    // 2) proj_in
    gemm_tc<256, 0, 0, 0><<<g256, 256, GSMEM>>>(h2b, wbf + W_PI, pi_b, nullptr, b1);
    // 3) dw3x3 + gelu
    dwgelu_kernel<<<BB * CC, 320>>>(b1, dw_w, dw_b, b2);
    // 4) fused (ffn1 @ fpw): 256 -> 512, gelu
    gemm_tc<256, 1, 0, 0><<<g512, 256, GSMEM>>>(b2, wbf + W_F1C, biasf1, nullptr, b1);
    // 5) combined (po @ ffn2): 512 -> 256, + res2 (h2 bf16)
    gemm_tc<512, 0, 2, 0><<<g256, 256, GSMEM>>>(b1, wbf + W_COMB, biasc, h2b, b2);
    // 6) post conv + outer residual (x fp32), fp32 out
    gemm_tc<256, 0, 1, 1><<<g256, 256, GSMEM>>>(b2, wbf + W_POST, post_b, x, out);
}